// round 4
// baseline (speedup 1.0000x reference)
#include <cuda_runtime.h>

// CosineSim3D: out[b,n,:300] = softmax_n( (a_n . sum_m b_m/|b_m|) / |a_n| )
// B=128, N=M=1024, D=300.
// 5 launches: k1 (stream b -> bsum partials), k1b (reduce partials, tiny),
//             k2 (stream a -> scores), k2b (softmax stats, tiny),
//             k3 (stream out). Main kernels use persistent single-wave grids.

static constexpr int BATCH = 128;
static constexpr int NROW  = 1024;
static constexpr int DDIM  = 300;
static constexpr int NQ    = 75;    // float4 per row
static constexpr int DPAD  = 304;   // padded feature dim
static constexpr int PB    = 32;    // row-chunks per batch (32 rows each)
static constexpr int RPP   = NROW / PB;        // 32 rows per work item
static constexpr int NITEMS = BATCH * PB;      // 4096 work items
static constexpr int THREADS = 256;
static constexpr int WARPS   = 8;
static constexpr int RPW     = RPP / WARPS;    // 4 rows per warp per item
static constexpr int RPI     = 2;
static constexpr int NSM       = 148;
static constexpr int BLK_PER_SM = 4;
static constexpr int GRID_MAIN  = NSM * BLK_PER_SM;  // 592, single wave

#define EPSV 1e-7f

// scratch (no allocations allowed)
__device__ float g_bpart[BATCH][PB][DPAD];
__device__ float g_bsum[BATCH][DPAD];
__device__ float g_scores[BATCH][NROW];
__device__ float g_stats[BATCH][2];   // {max, inv_sum}

__device__ __forceinline__ float warp_sum(float v) {
    #pragma unroll
    for (int o = 16; o > 0; o >>= 1) v += __shfl_xor_sync(0xffffffffu, v, o);
    return v;
}
__device__ __forceinline__ float warp_max(float v) {
    #pragma unroll
    for (int o = 16; o > 0; o >>= 1) v = fmaxf(v, __shfl_xor_sync(0xffffffffu, v, o));
    return v;
}
__device__ __forceinline__ float dot4(float4 x, float4 y) {
    return fmaf(x.x, y.x, fmaf(x.y, y.y, fmaf(x.z, y.z, x.w * y.w)));
}
__device__ __forceinline__ void axpy4(float4& acc, float4 q, float s) {
    acc.x = fmaf(q.x, s, acc.x);
    acc.y = fmaf(q.y, s, acc.y);
    acc.z = fmaf(q.z, s, acc.z);
    acc.w = fmaf(q.w, s, acc.w);
}

// ---------- K1: persistent; per item accumulate sum of b_m/||b_m|| ----------
__global__ void __launch_bounds__(THREADS, BLK_PER_SM)
k1_bsum(const float* __restrict__ gb)
{
    __shared__ __align__(16) float s_part[WARPS][DPAD];

    const int tid  = threadIdx.x;
    const int wid  = tid >> 5;
    const int lane = tid & 31;
    const bool has_q2 = lane < (NQ - 64);  // lane < 11
    const float4 f4z = make_float4(0.f, 0.f, 0.f, 0.f);

    for (int it = blockIdx.x; it < NITEMS; it += GRID_MAIN) {
        const int batch = it >> 5;           // / PB
        const int part  = it & (PB - 1);
        const float4* b4 = reinterpret_cast<const float4*>(gb)
                         + (size_t)batch * NROW * NQ;
        const int rbase = part * RPP + wid * RPW;

        float4 acc0 = f4z, acc1 = f4z, acc2 = f4z;

        #pragma unroll
        for (int i = 0; i < RPW; i += RPI) {
            float4 q0[RPI], q1[RPI], q2[RPI];
            #pragma unroll
            for (int r = 0; r < RPI; r++) {
                const float4* row = b4 + (size_t)(rbase + i + r) * NQ;
                q0[r] = row[lane];
                q1[r] = row[lane + 32];
                q2[r] = has_q2 ? row[lane + 64] : f4z;
            }
            #pragma unroll
            for (int r = 0; r < RPI; r++) {
                float ss = dot4(q0[r], q0[r]) + dot4(q1[r], q1[r]) + dot4(q2[r], q2[r]);
                ss = warp_sum(ss);
                float inv = 1.0f / sqrtf(fmaxf(ss, EPSV));
                axpy4(acc0, q0[r], inv);
                axpy4(acc1, q1[r], inv);
                axpy4(acc2, q2[r], inv);
            }
        }

        {
            float4* p4 = reinterpret_cast<float4*>(&s_part[wid][0]);
            p4[lane]      = acc0;
            p4[lane + 32] = acc1;
            if (has_q2) p4[lane + 64] = acc2;
        }
        __syncthreads();

        for (int d = tid; d < DDIM; d += THREADS) {
            float s = 0.f;
            #pragma unroll
            for (int w = 0; w < WARPS; w++) s += s_part[w][d];
            g_bpart[batch][part][d] = s;
        }
        __syncthreads();   // protect s_part before next item
    }
}

// ---------- K1b: tiny; reduce PB partials per batch ----------
__global__ void __launch_bounds__(THREADS)
k1b_reduce()
{
    const int batch = blockIdx.x;
    for (int d = threadIdx.x; d < DDIM; d += THREADS) {
        float s = 0.f;
        #pragma unroll
        for (int p = 0; p < PB; p++) s += g_bpart[batch][p][d];
        g_bsum[batch][d] = s;
    }
}

// ---------- K2: persistent; scores[n] = (a_n . bsum) / ||a_n|| ----------
__global__ void __launch_bounds__(THREADS, BLK_PER_SM)
k2_scores(const float* __restrict__ ga)
{
    const int tid  = threadIdx.x;
    const int wid  = tid >> 5;
    const int lane = tid & 31;
    const bool has_q2 = lane < (NQ - 64);
    const float4 f4z = make_float4(0.f, 0.f, 0.f, 0.f);

    for (int it = blockIdx.x; it < NITEMS; it += GRID_MAIN) {
        const int batch = it >> 5;
        const int part  = it & (PB - 1);

        const float4* bsum4 = reinterpret_cast<const float4*>(&g_bsum[batch][0]);
        float4 bs0 = bsum4[lane];
        float4 bs1 = bsum4[lane + 32];
        float4 bs2 = has_q2 ? bsum4[lane + 64] : f4z;

        const float4* a4 = reinterpret_cast<const float4*>(ga)
                         + (size_t)batch * NROW * NQ;
        const int rbase = part * RPP + wid * RPW;

        #pragma unroll
        for (int i = 0; i < RPW; i += RPI) {
            float4 q0[RPI], q1[RPI], q2[RPI];
            #pragma unroll
            for (int r = 0; r < RPI; r++) {
                const float4* row = a4 + (size_t)(rbase + i + r) * NQ;
                q0[r] = row[lane];
                q1[r] = row[lane + 32];
                q2[r] = has_q2 ? row[lane + 64] : f4z;
            }
            #pragma unroll
            for (int r = 0; r < RPI; r++) {
                float ss = dot4(q0[r], q0[r]) + dot4(q1[r], q1[r]) + dot4(q2[r], q2[r]);
                float dt = dot4(q0[r], bs0) + dot4(q1[r], bs1) + dot4(q2[r], bs2);
                #pragma unroll
                for (int o = 16; o > 0; o >>= 1) {
                    ss += __shfl_xor_sync(0xffffffffu, ss, o);
                    dt += __shfl_xor_sync(0xffffffffu, dt, o);
                }
                if (lane == 0)
                    g_scores[batch][rbase + i + r] = dt / sqrtf(fmaxf(ss, EPSV));
            }
        }
    }
}

// ---------- K2b: tiny; per-batch softmax stats (deterministic) ----------
__global__ void __launch_bounds__(THREADS)
k2b_stats()
{
    __shared__ float s_red[WARPS];
    const int batch = blockIdx.x;
    const int tid   = threadIdx.x;
    const int wid   = tid >> 5;
    const int lane  = tid & 31;

    float4 v = reinterpret_cast<const float4*>(&g_scores[batch][0])[tid];

    float mx = fmaxf(fmaxf(v.x, v.y), fmaxf(v.z, v.w));
    mx = warp_max(mx);
    if (lane == 0) s_red[wid] = mx;
    __syncthreads();
    if (wid == 0) {
        float m = (lane < WARPS) ? s_red[lane] : -3.4e38f;
        m = warp_max(m);
        if (lane == 0) s_red[0] = m;
    }
    __syncthreads();
    const float gmx = s_red[0];
    __syncthreads();

    float es = __expf(v.x - gmx) + __expf(v.y - gmx) +
               __expf(v.z - gmx) + __expf(v.w - gmx);
    es = warp_sum(es);
    if (lane == 0) s_red[wid] = es;
    __syncthreads();
    if (wid == 0) {
        float s = (lane < WARPS) ? s_red[lane] : 0.f;
        s = warp_sum(s);
        if (lane == 0) {
            g_stats[batch][0] = gmx;
            g_stats[batch][1] = 1.0f / s;
        }
    }
}

// ---------- K3: persistent; pure broadcast write ----------
__global__ void __launch_bounds__(THREADS, BLK_PER_SM)
k3_write(float* __restrict__ gout)
{
    const int tid  = threadIdx.x;
    const int wid  = tid >> 5;
    const int lane = tid & 31;
    const bool has_q2 = lane < (NQ - 64);

    for (int it = blockIdx.x; it < NITEMS; it += GRID_MAIN) {
        const int batch = it >> 5;
        const int part  = it & (PB - 1);

        const float gmx = g_stats[batch][0];
        const float inv = g_stats[batch][1];

        float4* o4 = reinterpret_cast<float4*>(gout) + (size_t)batch * NROW * NQ;
        const int rbase = part * RPP + wid * RPW;

        #pragma unroll
        for (int i = 0; i < RPW; i++) {
            const int row = rbase + i;
            const float p = __expf(g_scores[batch][row] - gmx) * inv;
            const float4 pv = make_float4(p, p, p, p);
            float4* orow = o4 + (size_t)row * NQ;
            orow[lane]      = pv;
            orow[lane + 32] = pv;
            if (has_q2) orow[lane + 64] = pv;
        }
    }
}

extern "C" void kernel_launch(void* const* d_in, const int* in_sizes, int n_in,
                              void* d_out, int out_size) {
    const float* a = (const float*)d_in[0];
    const float* b = (const float*)d_in[1];
    float* out = (float*)d_out;
    k1_bsum   <<<GRID_MAIN, THREADS>>>(b);
    k1b_reduce<<<BATCH, THREADS>>>();
    k2_scores <<<GRID_MAIN, THREADS>>>(a);
    k2b_stats <<<BATCH, THREADS>>>();
    k3_write  <<<GRID_MAIN, THREADS>>>(out);
}

// round 5
// speedup vs baseline: 1.1757x; 1.1757x over previous
#include <cuda_runtime.h>

// CosineSim3D: out[b,n,:300] = softmax_n( (a_n . sum_m b_m/|b_m|) / |a_n| )
// B=128, N=M=1024, D=300. Single fused kernel, 1 block per batch,
// 1024 threads (32 warps) for max memory-level parallelism.

static constexpr int BATCH   = 128;
static constexpr int NROW    = 1024;
static constexpr int DDIM    = 300;
static constexpr int NQ      = 75;   // float4 per row (300 floats)
static constexpr int DPAD    = 304;  // padded feature dim
static constexpr int THREADS = 1024;
static constexpr int WARPS   = 32;
static constexpr int RPW     = NROW / WARPS;  // 32 rows per warp
static constexpr int RPI     = 2;             // rows per load-batch

#define EPSV 1e-7f

__device__ __forceinline__ float warp_sum(float v) {
    #pragma unroll
    for (int o = 16; o > 0; o >>= 1) v += __shfl_xor_sync(0xffffffffu, v, o);
    return v;
}
__device__ __forceinline__ float warp_max(float v) {
    #pragma unroll
    for (int o = 16; o > 0; o >>= 1) v = fmaxf(v, __shfl_xor_sync(0xffffffffu, v, o));
    return v;
}
__device__ __forceinline__ float dot4(float4 x, float4 y) {
    return fmaf(x.x, y.x, fmaf(x.y, y.y, fmaf(x.z, y.z, x.w * y.w)));
}
__device__ __forceinline__ void axpy4(float4& acc, float4 q, float s) {
    acc.x = fmaf(q.x, s, acc.x);
    acc.y = fmaf(q.y, s, acc.y);
    acc.z = fmaf(q.z, s, acc.z);
    acc.w = fmaf(q.w, s, acc.w);
}

__global__ void __launch_bounds__(THREADS, 1)
cosine_sim3d_kernel(const float* __restrict__ ga,
                    const float* __restrict__ gb,
                    float* __restrict__ gout)
{
    __shared__ __align__(16) float s_part[WARPS][DPAD];  // 32 x 304 floats = 38.9 KB
    __shared__ __align__(16) float s_bsum[DPAD];
    __shared__ float s_scores[NROW];
    __shared__ float s_red[WARPS];

    const int batch = blockIdx.x;
    const int tid   = threadIdx.x;
    const int wid   = tid >> 5;
    const int lane  = tid & 31;
    const bool has_q2 = lane < (NQ - 64);  // lane < 11

    const float4* a4 = reinterpret_cast<const float4*>(ga) + (size_t)batch * NROW * NQ;
    const float4* b4 = reinterpret_cast<const float4*>(gb) + (size_t)batch * NROW * NQ;
    float4*       o4 = reinterpret_cast<float4*>(gout)     + (size_t)batch * NROW * NQ;

    const int rbase = wid * RPW;
    const float4 f4z = make_float4(0.f, 0.f, 0.f, 0.f);

    // ---------------- Phase 1: bsum = sum_m b[m,:] / ||b[m,:]|| ----------------
    float4 acc0 = f4z, acc1 = f4z, acc2 = f4z;

    #pragma unroll 1
    for (int i = 0; i < RPW; i += RPI) {
        float4 q0[RPI], q1[RPI], q2[RPI];
        #pragma unroll
        for (int r = 0; r < RPI; r++) {
            const float4* row = b4 + (size_t)(rbase + i + r) * NQ;
            q0[r] = row[lane];
            q1[r] = row[lane + 32];
            q2[r] = has_q2 ? row[lane + 64] : f4z;
        }
        #pragma unroll
        for (int r = 0; r < RPI; r++) {
            float ss = dot4(q0[r], q0[r]) + dot4(q1[r], q1[r]) + dot4(q2[r], q2[r]);
            ss = warp_sum(ss);
            float inv = 1.0f / sqrtf(fmaxf(ss, EPSV));
            axpy4(acc0, q0[r], inv);
            axpy4(acc1, q1[r], inv);
            axpy4(acc2, q2[r], inv);
        }
    }

    {
        float4* p4 = reinterpret_cast<float4*>(&s_part[wid][0]);
        p4[lane]      = acc0;
        p4[lane + 32] = acc1;
        if (has_q2) p4[lane + 64] = acc2;
    }
    __syncthreads();

    // deterministic cross-warp reduction (300 < 1024 threads)
    if (tid < DDIM) {
        float s = 0.f;
        #pragma unroll
        for (int w = 0; w < WARPS; w++) s += s_part[w][tid];
        s_bsum[tid] = s;
    }
    __syncthreads();

    // ---------------- Phase 2: scores[n] = (a_n . bsum) / ||a_n|| ----------------
    float4 bs0, bs1, bs2;
    {
        const float4* bsum4 = reinterpret_cast<const float4*>(s_bsum);
        bs0 = bsum4[lane];
        bs1 = bsum4[lane + 32];
        bs2 = has_q2 ? bsum4[lane + 64] : f4z;
    }

    #pragma unroll 1
    for (int i = 0; i < RPW; i += RPI) {
        float4 q0[RPI], q1[RPI], q2[RPI];
        #pragma unroll
        for (int r = 0; r < RPI; r++) {
            const float4* row = a4 + (size_t)(rbase + i + r) * NQ;
            q0[r] = row[lane];
            q1[r] = row[lane + 32];
            q2[r] = has_q2 ? row[lane + 64] : f4z;
        }
        #pragma unroll
        for (int r = 0; r < RPI; r++) {
            float ss = dot4(q0[r], q0[r]) + dot4(q1[r], q1[r]) + dot4(q2[r], q2[r]);
            float dt = dot4(q0[r], bs0) + dot4(q1[r], bs1) + dot4(q2[r], bs2);
            #pragma unroll
            for (int o = 16; o > 0; o >>= 1) {
                ss += __shfl_xor_sync(0xffffffffu, ss, o);
                dt += __shfl_xor_sync(0xffffffffu, dt, o);
            }
            if (lane == 0)
                s_scores[rbase + i + r] = dt / sqrtf(fmaxf(ss, EPSV));
        }
    }
    __syncthreads();

    // ---------------- Phase 3: softmax over n (per batch) ----------------
    float v0 = s_scores[tid];  // 1024 threads, 1 score each

    float mx = warp_max(v0);
    if (lane == 0) s_red[wid] = mx;
    __syncthreads();
    if (wid == 0) {
        float m = s_red[lane];           // WARPS == 32 == lanes
        m = warp_max(m);
        if (lane == 0) s_red[0] = m;
    }
    __syncthreads();
    const float gmx = s_red[0];
    __syncthreads();  // all reads of s_red[0] done before reuse

    float e0 = __expf(v0 - gmx);
    float sm = warp_sum(e0);
    if (lane == 0) s_red[wid] = sm;
    __syncthreads();
    if (wid == 0) {
        float s = s_red[lane];
        s = warp_sum(s);
        if (lane == 0) s_red[0] = s;
    }
    __syncthreads();
    const float inv_sum = 1.0f / s_red[0];

    s_scores[tid] = e0 * inv_sum;
    __syncthreads();

    // ---------------- Phase 4: tiled broadcast write ----------------
    #pragma unroll 1
    for (int i = 0; i < RPW; i++) {
        const int row = rbase + i;
        const float p = s_scores[row];
        const float4 v = make_float4(p, p, p, p);
        float4* orow = o4 + (size_t)row * NQ;
        orow[lane]      = v;
        orow[lane + 32] = v;
        if (has_q2) orow[lane + 64] = v;
    }
}

extern "C" void kernel_launch(void* const* d_in, const int* in_sizes, int n_in,
                              void* d_out, int out_size) {
    const float* a = (const float*)d_in[0];
    const float* b = (const float*)d_in[1];
    float* out = (float*)d_out;
    cosine_sim3d_kernel<<<BATCH, THREADS>>>(a, b, out);
}

// round 6
// speedup vs baseline: 1.1826x; 1.0059x over previous
#include <cuda_runtime.h>
#include <cstdint>

// CosineSim3D: out[b,n,:300] = softmax_n( (a_n . sum_m b_m/|b_m|) / |a_n| )
// B=128, N=M=1024, D=300. Single fused kernel, 1 block/batch, 1024 threads.
// cp.async ring (3 stages x 32 rows) lifts per-SM in-flight bytes to ~77KB
// so DRAM saturates despite the 64-reg ceiling at 1024 threads.

static constexpr int BATCH     = 128;
static constexpr int NROW      = 1024;
static constexpr int DDIM      = 300;
static constexpr int NQ        = 75;                  // float4 per row
static constexpr int DPAD      = 304;
static constexpr int THREADS   = 1024;
static constexpr int WARPS     = 32;
static constexpr int RPW       = NROW / WARPS;        // 32 rows/warp (write phase)
static constexpr int TILE_ROWS = 32;                  // one row per warp per tile
static constexpr int TILES     = NROW / TILE_ROWS;    // 32
static constexpr int STAGES    = 3;
static constexpr int TILE_F4   = TILE_ROWS * NQ;      // 2400 float4
static constexpr int TILE_B    = TILE_F4 * 16;        // 38400 bytes

// dynamic smem layout (bytes)
static constexpr int RING_B    = STAGES * TILE_B;             // 115200
static constexpr int PART_B    = WARPS * DPAD * 4;            // 38912
static constexpr int OFF_PART  = RING_B;
static constexpr int OFF_BSUM  = OFF_PART + PART_B;           // 304 floats
static constexpr int OFF_SCORE = OFF_BSUM + DPAD * 4;         // 1024 floats
static constexpr int OFF_RED   = OFF_SCORE + NROW * 4;        // 32 floats
static constexpr int SMEM_B    = OFF_RED + WARPS * 4;         // ~159.6 KB

#define EPSV 1e-7f

__device__ __forceinline__ void cpa16(uint32_t dst_smem, const void* src) {
    asm volatile("cp.async.cg.shared.global [%0], [%1], 16;\n"
                 :: "r"(dst_smem), "l"(src));
}
__device__ __forceinline__ void cpa_commit() {
    asm volatile("cp.async.commit_group;\n");
}
template <int N>
__device__ __forceinline__ void cpa_wait() {
    asm volatile("cp.async.wait_group %0;\n" :: "n"(N));
}

__device__ __forceinline__ float warp_sum(float v) {
    #pragma unroll
    for (int o = 16; o > 0; o >>= 1) v += __shfl_xor_sync(0xffffffffu, v, o);
    return v;
}
__device__ __forceinline__ float warp_max(float v) {
    #pragma unroll
    for (int o = 16; o > 0; o >>= 1) v = fmaxf(v, __shfl_xor_sync(0xffffffffu, v, o));
    return v;
}
__device__ __forceinline__ float dot4(float4 x, float4 y) {
    return fmaf(x.x, y.x, fmaf(x.y, y.y, fmaf(x.z, y.z, x.w * y.w)));
}
__device__ __forceinline__ void axpy4(float4& acc, float4 q, float s) {
    acc.x = fmaf(q.x, s, acc.x);
    acc.y = fmaf(q.y, s, acc.y);
    acc.z = fmaf(q.z, s, acc.z);
    acc.w = fmaf(q.w, s, acc.w);
}

// all threads cooperatively issue one tile's cp.asyncs into a ring stage
__device__ __forceinline__ void issue_tile(uint32_t ring_u32, int stage,
                                           const float4* src_tile, int tid) {
    const uint32_t dst = ring_u32 + stage * TILE_B;
    #pragma unroll
    for (int i = tid; i < TILE_F4; i += THREADS)
        cpa16(dst + i * 16, src_tile + i);
}

__global__ void __launch_bounds__(THREADS, 1)
cosine_sim3d_kernel(const float* __restrict__ ga,
                    const float* __restrict__ gb,
                    float* __restrict__ gout)
{
    extern __shared__ __align__(16) char smem[];
    float* ring     = reinterpret_cast<float*>(smem);
    float* s_part   = reinterpret_cast<float*>(smem + OFF_PART);   // [32][304]
    float* s_bsum   = reinterpret_cast<float*>(smem + OFF_BSUM);
    float* s_scores = reinterpret_cast<float*>(smem + OFF_SCORE);
    float* s_red    = reinterpret_cast<float*>(smem + OFF_RED);
    const uint32_t ring_u32 =
        (uint32_t)__cvta_generic_to_shared(ring);

    const int batch = blockIdx.x;
    const int tid   = threadIdx.x;
    const int wid   = tid >> 5;
    const int lane  = tid & 31;
    const bool has_q2 = lane < (NQ - 64);  // lane < 11
    const float4 f4z = make_float4(0.f, 0.f, 0.f, 0.f);

    const float4* a4 = reinterpret_cast<const float4*>(ga) + (size_t)batch * NROW * NQ;
    const float4* b4 = reinterpret_cast<const float4*>(gb) + (size_t)batch * NROW * NQ;
    float4*       o4 = reinterpret_cast<float4*>(gout)     + (size_t)batch * NROW * NQ;

    // ================= Phase 1: bsum = sum_m b_m / ||b_m|| =================
    float4 acc0 = f4z, acc1 = f4z, acc2 = f4z;

    #pragma unroll
    for (int s = 0; s < STAGES; s++) {
        issue_tile(ring_u32, s, b4 + (size_t)s * TILE_F4, tid);
        cpa_commit();
    }

    #pragma unroll 1
    for (int t = 0; t < TILES; t++) {
        cpa_wait<STAGES - 1>();
        __syncthreads();

        // warp w processes row (t*32 + w) from stage t%3
        const float4* r4 = reinterpret_cast<const float4*>(
            ring + (size_t)(t % STAGES) * (TILE_B / 4) + (size_t)wid * DDIM);
        float4 q0 = r4[lane];
        float4 q1 = r4[lane + 32];
        float4 q2 = has_q2 ? r4[lane + 64] : f4z;

        float ss = dot4(q0, q0) + dot4(q1, q1) + dot4(q2, q2);
        ss = warp_sum(ss);
        float inv = 1.0f / sqrtf(fmaxf(ss, EPSV));
        axpy4(acc0, q0, inv);
        axpy4(acc1, q1, inv);
        axpy4(acc2, q2, inv);

        __syncthreads();
        if (t + STAGES < TILES)
            issue_tile(ring_u32, t % STAGES, b4 + (size_t)(t + STAGES) * TILE_F4, tid);
        cpa_commit();  // uniform accounting (empty group near tail)
    }
    cpa_wait<0>();

    {
        float4* p4 = reinterpret_cast<float4*>(s_part + (size_t)wid * DPAD);
        p4[lane]      = acc0;
        p4[lane + 32] = acc1;
        if (has_q2) p4[lane + 64] = acc2;
    }
    __syncthreads();

    if (tid < DDIM) {
        float s = 0.f;
        #pragma unroll
        for (int w = 0; w < WARPS; w++) s += s_part[(size_t)w * DPAD + tid];
        s_bsum[tid] = s;
    }
    __syncthreads();

    // ================= Phase 2: scores[n] = (a_n . bsum) / ||a_n|| =========
    float4 bs0, bs1, bs2;
    {
        const float4* bsum4 = reinterpret_cast<const float4*>(s_bsum);
        bs0 = bsum4[lane];
        bs1 = bsum4[lane + 32];
        bs2 = has_q2 ? bsum4[lane + 64] : f4z;
    }

    #pragma unroll
    for (int s = 0; s < STAGES; s++) {
        issue_tile(ring_u32, s, a4 + (size_t)s * TILE_F4, tid);
        cpa_commit();
    }

    #pragma unroll 1
    for (int t = 0; t < TILES; t++) {
        cpa_wait<STAGES - 1>();
        __syncthreads();

        const float4* r4 = reinterpret_cast<const float4*>(
            ring + (size_t)(t % STAGES) * (TILE_B / 4) + (size_t)wid * DDIM);
        float4 q0 = r4[lane];
        float4 q1 = r4[lane + 32];
        float4 q2 = has_q2 ? r4[lane + 64] : f4z;

        float ss = dot4(q0, q0) + dot4(q1, q1) + dot4(q2, q2);
        float dt = dot4(q0, bs0) + dot4(q1, bs1) + dot4(q2, bs2);
        #pragma unroll
        for (int o = 16; o > 0; o >>= 1) {
            ss += __shfl_xor_sync(0xffffffffu, ss, o);
            dt += __shfl_xor_sync(0xffffffffu, dt, o);
        }
        if (lane == 0)
            s_scores[t * TILE_ROWS + wid] = dt / sqrtf(fmaxf(ss, EPSV));

        __syncthreads();
        if (t + STAGES < TILES)
            issue_tile(ring_u32, t % STAGES, a4 + (size_t)(t + STAGES) * TILE_F4, tid);
        cpa_commit();
    }
    cpa_wait<0>();
    __syncthreads();

    // ================= Phase 3: softmax over n =================
    float v0 = s_scores[tid];

    float mx = warp_max(v0);
    if (lane == 0) s_red[wid] = mx;
    __syncthreads();
    if (wid == 0) {
        float m = s_red[lane];           // WARPS == 32
        m = warp_max(m);
        if (lane == 0) s_red[0] = m;
    }
    __syncthreads();
    const float gmx = s_red[0];
    __syncthreads();

    float e0 = __expf(v0 - gmx);
    float sm = warp_sum(e0);
    if (lane == 0) s_red[wid] = sm;
    __syncthreads();
    if (wid == 0) {
        float s = s_red[lane];
        s = warp_sum(s);
        if (lane == 0) s_red[0] = s;
    }
    __syncthreads();
    const float inv_sum = 1.0f / s_red[0];

    s_scores[tid] = e0 * inv_sum;
    __syncthreads();

    // ================= Phase 4: tiled broadcast write =================
    const int rbase = wid * RPW;
    #pragma unroll 1
    for (int i = 0; i < RPW; i++) {
        const int row = rbase + i;
        const float p = s_scores[row];
        const float4 v = make_float4(p, p, p, p);
        float4* orow = o4 + (size_t)row * NQ;
        orow[lane]      = v;
        orow[lane + 32] = v;
        if (has_q2) orow[lane + 64] = v;
    }
}

extern "C" void kernel_launch(void* const* d_in, const int* in_sizes, int n_in,
                              void* d_out, int out_size) {
    const float* a = (const float*)d_in[0];
    const float* b = (const float*)d_in[1];
    float* out = (float*)d_out;
    static bool attr_set = false;
    if (!attr_set) {
        cudaFuncSetAttribute(cosine_sim3d_kernel,
                             cudaFuncAttributeMaxDynamicSharedMemorySize, SMEM_B);
        attr_set = true;
    }
    cosine_sim3d_kernel<<<BATCH, THREADS, SMEM_B>>>(a, b, out);
}